// round 11
// baseline (speedup 1.0000x reference)
#include <cuda_runtime.h>
#include <cuda_bf16.h>
#include <math.h>
#include <stdint.h>

#define BB 4
#define LQ 128
#define LF 64
#define NW 2
#define NFR 8
#define EE 128
#define DD 128
#define VV 64
#define WF (NW*NFR)   // 16

// ---- output layout (concatenated in reference tuple order) ----
#define OUT_FRAGCODE  0
#define OUT_QUERYCODE (BB*WF*DD)
#define OUT_SELFATT   (2*BB*WF*DD)
#define OUT_GATE      (2*BB*WF*DD + BB*WF*LF)
#define OUT_QUERY     (OUT_GATE + BB*WF*LQ)

// ---- scratch ----
__device__ float g_fproj[BB*WF*LF*DD];   // projected fragment (b,wf,lf,d)
__device__ float g_qatt [BB*LQ*VV];      // q_att (b,lq,v)
__device__ float g_fatt [BB*WF*LF*VV];   // f_att (b,wf,lf,v)
__device__ float g_pmax [512*64*64];     // partial maxes [bwf*8+lqh*4+lfq][64][64] (8MB)
__device__ float g_e2n  [BB*WF*LQ];      // normalized exp(qf@val_w)*mask

// bf16 split helpers
__device__ __forceinline__ uint32_t pack_bf16x2(float lo_val, float hi_val) {
    uint32_t r;
    asm("cvt.rn.bf16x2.f32 %0, %1, %2;" : "=r"(r) : "f"(hi_val), "f"(lo_val));
    return r;
}
__device__ __forceinline__ float bf16lo_f32(uint32_t u) { return __uint_as_float(u << 16); }
__device__ __forceinline__ float bf16hi_f32(uint32_t u) { return __uint_as_float(u & 0xffff0000u); }
__device__ __forceinline__ void split2(float x0, float x1, uint32_t& hi, uint32_t& lo) {
    hi = pack_bf16x2(x0, x1);
    float r0 = x0 - bf16lo_f32(hi);
    float r1 = x1 - bf16hi_f32(hi);
    lo = pack_bf16x2(r0, r1);
}

// mma.sync m16n8k16 row.col f32.bf16.bf16.f32
__device__ __forceinline__ void mma16816(float* c, const uint32_t* a, const uint32_t* b) {
    asm volatile(
        "mma.sync.aligned.m16n8k16.row.col.f32.bf16.bf16.f32 "
        "{%0,%1,%2,%3}, {%4,%5,%6,%7}, {%8,%9}, {%0,%1,%2,%3};"
        : "+f"(c[0]), "+f"(c[1]), "+f"(c[2]), "+f"(c[3])
        : "r"(a[0]), "r"(a[1]), "r"(a[2]), "r"(a[3]), "r"(b[0]), "r"(b[1]));
}

// ============================================================
// Kernel A: fused projection + attention-weight GEMMs, tiled.
// ============================================================
__global__ void __launch_bounds__(256) k_projatt(
    const float* __restrict__ query, const float* __restrict__ frag,
    const float* __restrict__ W, const float* __restrict__ bias,
    const float* __restrict__ qattW, const float* __restrict__ fattW,
    float* __restrict__ outq) {
    extern __shared__ float s[];
    float* Wsh  = s;            // 16384
    float* AWsh = s + 16384;    // 8192
    float* xsh  = s + 24576;    // 1024
    float* psh  = s + 25600;    // 1024   total 26624 floats
    int g = blockIdx.x;
    int tid = threadIdx.x;
    bool isq = (g < 64);

    {
        const float4* Wv = (const float4*)W;
        float4* Ws = (float4*)Wsh;
        #pragma unroll
        for (int i = 0; i < 16; i++) Ws[tid + 256*i] = Wv[tid + 256*i];
        const float4* Av = (const float4*)(isq ? qattW : fattW);
        float4* As = (float4*)AWsh;
        #pragma unroll
        for (int i = 0; i < 8; i++) As[tid + 256*i] = Av[tid + 256*i];
        const float* src = isq ? (query + (size_t)g*8*EE)
                               : (frag  + (size_t)(g-64)*8*EE);
        ((float4*)xsh)[tid] = ((const float4*)src)[tid];
    }
    __syncthreads();

    {
        int j = tid & 127, rh = tid >> 7;
        float bj = __ldg(&bias[j]);
        float a0 = bj, a1 = bj, a2 = bj, a3 = bj;
        #pragma unroll 4
        for (int d = 0; d < EE; d++) {
            float w = Wsh[d*DD + j];
            a0 = fmaf(xsh[(rh+0)*EE + d], w, a0);
            a1 = fmaf(xsh[(rh+2)*EE + d], w, a1);
            a2 = fmaf(xsh[(rh+4)*EE + d], w, a2);
            a3 = fmaf(xsh[(rh+6)*EE + d], w, a3);
        }
        psh[(rh+0)*DD + j] = a0; psh[(rh+2)*DD + j] = a1;
        psh[(rh+4)*DD + j] = a2; psh[(rh+6)*DD + j] = a3;
        float* dst = isq ? (outq + (size_t)g*8*DD)
                         : (g_fproj + (size_t)(g-64)*8*DD);
        dst[(rh+0)*DD + j] = a0; dst[(rh+2)*DD + j] = a1;
        dst[(rh+4)*DD + j] = a2; dst[(rh+6)*DD + j] = a3;
    }
    __syncthreads();

    {
        int j2 = tid & 63, r2 = tid >> 6;
        float a0 = 0.f, a1 = 0.f;
        #pragma unroll 4
        for (int d = 0; d < DD; d++) {
            float w = AWsh[d*VV + j2];
            a0 = fmaf(psh[(r2+0)*DD + d], w, a0);
            a1 = fmaf(psh[(r2+4)*DD + d], w, a1);
        }
        float* dst = isq ? (g_qatt + (size_t)g*8*VV)
                         : (g_fatt + (size_t)(g-64)*8*VV);
        dst[(r2+0)*VV + j2] = a0;
        dst[(r2+4)*VV + j2] = a1;
    }
}

// ============================================================
// Kernel B: fragment self-attention softmax + frag_code
// ============================================================
__global__ void k_fragcode(const float* __restrict__ saW,
                           const float* __restrict__ fmask,
                           float* __restrict__ out) {
    int bwf = blockIdx.x;
    int w = (bwf % WF) / NFR;
    const float* fbase = g_fproj + (size_t)bwf*LF*DD;
    __shared__ float att[LF];
    __shared__ float s_inv;
    int t = threadIdx.x;
    if (t < LF) {
        const float* fr = fbase + t*DD;
        const float* sw = saW + w*DD;
        float acc = 0.f;
        #pragma unroll 8
        for (int d = 0; d < DD; d++) acc += fr[d]*sw[d];
        att[t] = expf(acc) * fmask[bwf*LF + t];
    }
    __syncthreads();
    if (t == 0) {
        float ss = 0.f;
        for (int l = 0; l < LF; l++) ss += att[l];
        s_inv = 1.f / (ss + 1e-7f);
    }
    __syncthreads();
    float inv = s_inv;
    if (t < LF) out[OUT_SELFATT + bwf*LF + t] = att[t]*inv;
    float acc = 0.f;
    #pragma unroll 8
    for (int l = 0; l < LF; l++) acc += att[l]*inv*fbase[l*DD + t];
    out[OUT_FRAGCODE + bwf*DD + t] = acc;
}

// ============================================================
// Kernel C (hot, HMMA): per (bwf, lq-half64, lf-quarter16):
//   partial max over lf of (f_att + q @ (f_lf ⊙ W_qf))
// A = q 64x128 split bf16 hi/lo ONCE, fragments register-resident.
// B' = f⊙W split hi/lo converted DIRECTLY INTO FRAGMENT LAYOUT:
//   uint4 {bh0,bh1,bl0,bl1} at j = k*256 + ng*128 + t*32 + lane
//   (v = ng*32 + t*8 + (lane>>2), word c = k*8 + (lane&3), c+4)
// so each mma b-operand is ONE coalesced LDS.128 (was 4x LDS.32).
// Double-buffered B' (1 sync per lf); buffer 1 aliases the A-staging
// region (A only needed until fragment load; ordering via syncs).
// 3-pass split GEMM (Ahi*Bhi + Ahi*Blo + Alo*Bhi), fp32 accum.
// 8 warps: warp = (m-strip 16 of 64) x (n-half 32 of 64).
// ============================================================
// smem word offsets
#define QW_WT   0                      // W transposed [64][130] = 8320 words
#define QW_A    8320                   // Ah [64][68] = 4352, Al = 4352  (8704 words)
#define QW_BF0  (QW_A + 8704)          // Bf0: 2048 uint4 = 8192 words
#define QW_TOT  (QW_BF0 + 8192)        // 25216 words = 100864 B
// Bf1 aliases QW_A (needs 8192 <= 8704 words; 4-word aligned)

__global__ void __launch_bounds__(256) k_qf_mma(
    const float* __restrict__ qfW, const float* __restrict__ outq) {
    extern __shared__ float s[];
    float* Wt = s + QW_WT;                       // [v][130] fp32
    uint32_t* Ah = (uint32_t*)(s + QW_A);        // [row][68]
    uint32_t* Al = Ah + 4352;
    uint4* Bf0 = (uint4*)(s + QW_BF0);
    uint4* Bf1 = (uint4*)(s + QW_A);             // alias (safe after A-frag load)

    int blk = blockIdx.x;            // 512 = bwf(64) x lqh(2) x lfq(4)
    int lfq = blk & 3;
    int lqh = (blk >> 2) & 1;
    int bwf = blk >> 3;
    int b = bwf >> 4;
    int lfbase = lfq * 16;
    int tid = threadIdx.x, lane = tid & 31, wid = tid >> 5;
    int m0 = (wid & 3) * 16;         // m-strip within 64
    int ng = wid >> 2;               // n-group (0/1), n0 = ng*32

    // stage W transposed: Wt[v][d]
    for (int idx = tid; idx < DD*VV; idx += 256) {
        int d = idx >> 6, v = idx & 63;
        Wt[v*130 + d] = qfW[idx];
    }
    // convert A (q tile 64x128) -> bf16 hi/lo words [row][68]
    for (int idx = tid; idx < 64*64; idx += 256) {
        int row = idx >> 6, cp = idx & 63;
        float2 qv = *(const float2*)&outq[((size_t)(b*LQ + lqh*64 + row))*DD + cp*2];
        uint32_t hi, lo;
        split2(qv.x, qv.y, hi, lo);
        Ah[row*68 + cp] = hi;
        Al[row*68 + cp] = lo;
    }
    __syncthreads();

    // load A fragments (register-resident for all lf)
    uint32_t ah[8][4], al[8][4];
    {
        int r = m0 + (lane >> 2);
        #pragma unroll
        for (int k = 0; k < 8; k++) {
            int c = k*8 + (lane & 3);
            ah[k][0] = Ah[r*68 + c];       ah[k][1] = Ah[(r+8)*68 + c];
            ah[k][2] = Ah[r*68 + c + 4];   ah[k][3] = Ah[(r+8)*68 + c + 4];
            al[k][0] = Al[r*68 + c];       al[k][1] = Al[(r+8)*68 + c];
            al[k][2] = Al[r*68 + c + 4];   al[k][3] = Al[(r+8)*68 + c + 4];
        }
    }

    // prologue: convert B'(lfbase) into Bf0 (does not touch A region)
    {
        const float* fptr = g_fproj + ((size_t)bwf*LF + lfbase)*DD;
        #pragma unroll
        for (int i = 0; i < 8; i++) {
            int j = tid + 256*i;
            int ln = j & 31, t = (j >> 5) & 3, g2 = (j >> 7) & 1, k = j >> 8;
            int v = g2*32 + t*8 + (ln >> 2);
            int cp0 = k*8 + (ln & 3), cp1 = cp0 + 4;
            float2 w0 = *(const float2*)&Wt[v*130 + cp0*2];
            float2 w1 = *(const float2*)&Wt[v*130 + cp1*2];
            float2 f0 = *(const float2*)&fptr[cp0*2];
            float2 f1 = *(const float2*)&fptr[cp1*2];
            uint32_t h0, l0, h1, l1;
            split2(w0.x*f0.x, w0.y*f0.y, h0, l0);
            split2(w1.x*f1.x, w1.y*f1.y, h1, l1);
            Bf0[j] = make_uint4(h0, h1, l0, l1);
        }
    }
    __syncthreads();   // A-frag loads done by all warps; Bf0 ready

    float mx[4][4];
    #pragma unroll
    for (int t = 0; t < 4; t++)
        #pragma unroll
        for (int i = 0; i < 4; i++) mx[t][i] = -INFINITY;

    for (int k16 = 0; k16 < 16; k16++) {
        int lf = lfbase + k16;

        // convert next lf into the other buffer (overlaps other warps' MMA)
        if (k16 < 15) {
            uint4* Bn = ((k16+1) & 1) ? Bf1 : Bf0;
            const float* fptr = g_fproj + ((size_t)bwf*LF + lf + 1)*DD;
            #pragma unroll
            for (int i = 0; i < 8; i++) {
                int j = tid + 256*i;
                int ln = j & 31, t = (j >> 5) & 3, g2 = (j >> 7) & 1, k = j >> 8;
                int v = g2*32 + t*8 + (ln >> 2);
                int cp0 = k*8 + (ln & 3), cp1 = cp0 + 4;
                float2 w0 = *(const float2*)&Wt[v*130 + cp0*2];
                float2 w1 = *(const float2*)&Wt[v*130 + cp1*2];
                float2 f0 = *(const float2*)&fptr[cp0*2];
                float2 f1 = *(const float2*)&fptr[cp1*2];
                uint32_t h0, l0, h1, l1;
                split2(w0.x*f0.x, w0.y*f0.y, h0, l0);
                split2(w1.x*f1.x, w1.y*f1.y, h1, l1);
                Bn[j] = make_uint4(h0, h1, l0, l1);
            }
        }

        // 3-pass split GEMM on buf[k16&1], C[16x32] per warp
        const uint4* Bc = (k16 & 1) ? Bf1 : Bf0;
        float cc[4][4];
        #pragma unroll
        for (int t = 0; t < 4; t++)
            #pragma unroll
            for (int i = 0; i < 4; i++) cc[t][i] = 0.f;

        #pragma unroll
        for (int k = 0; k < 8; k++) {
            #pragma unroll
            for (int t = 0; t < 4; t++) {
                uint4 q4 = Bc[k*256 + ng*128 + t*32 + lane];
                uint32_t bh[2] = {q4.x, q4.y};
                uint32_t bl[2] = {q4.z, q4.w};
                mma16816(cc[t], ah[k], bh);
                mma16816(cc[t], ah[k], bl);
                mma16816(cc[t], al[k], bh);
            }
        }

        // running max of (cc + f_att)
        const float* fa = g_fatt + ((size_t)bwf*LF + lf)*VV;
        #pragma unroll
        for (int t = 0; t < 4; t++) {
            int col = ng*32 + t*8 + (lane & 3)*2;
            float2 f2 = *(const float2*)&fa[col];
            mx[t][0] = fmaxf(mx[t][0], cc[t][0] + f2.x);
            mx[t][1] = fmaxf(mx[t][1], cc[t][1] + f2.y);
            mx[t][2] = fmaxf(mx[t][2], cc[t][2] + f2.x);
            mx[t][3] = fmaxf(mx[t][3], cc[t][3] + f2.y);
        }

        __syncthreads();   // all reads of buf[k16&1] done; next buffer published
    }

    // write partial-max tile [64][64]
    float* outp = g_pmax + (size_t)blk * 4096;
    int r0 = m0 + (lane >> 2);
    #pragma unroll
    for (int t = 0; t < 4; t++) {
        int col = ng*32 + t*8 + (lane & 3)*2;
        *(float2*)&outp[r0*64 + col]     = make_float2(mx[t][0], mx[t][1]);
        *(float2*)&outp[(r0+8)*64 + col] = make_float2(mx[t][2], mx[t][3]);
    }
}

// ============================================================
// Kernel D1: per bwf — combine 4 lf-quarters, + q_att, gate/val
// dots, sigmoid/exp, parallel softmax-normalize over LQ.
// 512 threads = lq(128) x vq(4) for 4x MLP on the g_pmax stream.
// ============================================================
__global__ void __launch_bounds__(512) k_fin_a(
    const float* __restrict__ gate_w,
    const float* __restrict__ val_w,
    const float* __restrict__ qmask,
    float* __restrict__ out) {
    int bwf = blockIdx.x;
    int b = bwf >> 4;
    int tid = threadIdx.x;
    int lq = tid & 127, vq = tid >> 7;
    __shared__ float gsh[4][LQ];
    __shared__ float vsh[4][LQ];
    __shared__ float esh[LQ];
    __shared__ float red[LQ];

    int lqh = lq >> 6, r = lq & 63;
    const float* base = g_pmax + ((size_t)(bwf*8 + lqh*4)) * 4096 + r*64;
    const float4* qa = (const float4*)(g_qatt + (size_t)(b*LQ + lq)*VV);
    const float4* gw = (const float4*)gate_w;
    const float4* vw = (const float4*)val_w;

    float gs = 0.f, vs = 0.f;
    #pragma unroll
    for (int i = vq*4; i < vq*4 + 4; i++) {
        float4 a0 = *(const float4*)&base[i*4];
        float4 a1 = *(const float4*)&base[4096 + i*4];
        float4 a2 = *(const float4*)&base[2*4096 + i*4];
        float4 a3 = *(const float4*)&base[3*4096 + i*4];
        float4 q = qa[i], g4 = gw[i], v4 = vw[i];
        float mxv = fmaxf(fmaxf(a0.x, a1.x), fmaxf(a2.x, a3.x)) + q.x;
        float myv = fmaxf(fmaxf(a0.y, a1.y), fmaxf(a2.y, a3.y)) + q.y;
        float mzv = fmaxf(fmaxf(a0.z, a1.z), fmaxf(a2.z, a3.z)) + q.z;
        float mwv = fmaxf(fmaxf(a0.w, a1.w), fmaxf(a2.w, a3.w)) + q.w;
        gs += mxv*g4.x + myv*g4.y + mzv*g4.z + mwv*g4.w;
        vs += mxv*v4.x + myv*v4.y + mzv*v4.z + mwv*v4.w;
    }
    gsh[vq][lq] = gs;
    vsh[vq][lq] = vs;
    __syncthreads();

    if (tid < LQ) {
        float gsum = gsh[0][tid] + gsh[1][tid] + gsh[2][tid] + gsh[3][tid];
        float vsum = vsh[0][tid] + vsh[1][tid] + vsh[2][tid] + vsh[3][tid];
        float qm = qmask[b*LQ + tid];
        out[OUT_GATE + bwf*LQ + tid] = (1.f / (1.f + expf(-gsum))) * qm;
        float e2 = expf(vsum) * qm;
        esh[tid] = e2;
        red[tid] = e2;
    }
    __syncthreads();
    #pragma unroll
    for (int off = 64; off > 0; off >>= 1) {
        if (tid < off) red[tid] += red[tid + off];
        __syncthreads();
    }
    if (tid < LQ) {
        float inv = 1.f / (red[0] + 1e-7f);
        g_e2n[bwf*LQ + tid] = esh[tid] * inv;
    }
}

// ============================================================
// Kernel D2: query_code[b,wf,d] = sum_l e2n[b,wf,l] * q[b,l,d]
// ============================================================
__global__ void k_fin_b(const float* __restrict__ outq,
                        float* __restrict__ out) {
    __shared__ float qs[LQ*8];       // q slice [l][dd]
    __shared__ float es[WF*LQ];      // e2n [wf][l]
    int blk = blockIdx.x;
    int seg = blk & 15, b = blk >> 4;
    int t = threadIdx.x;

    for (int idx = t; idx < LQ*8; idx += 128) {
        int l = idx >> 3, dd = idx & 7;
        qs[l*8 + dd] = outq[((size_t)(b*LQ + l))*DD + seg*8 + dd];
    }
    for (int idx = t; idx < WF*LQ; idx += 128) {
        int wf = idx >> 7, l = idx & 127;
        es[wf*LQ + l] = g_e2n[(b*WF + wf)*LQ + l];
    }
    __syncthreads();

    int wf = t >> 3, dd = t & 7;
    float acc = 0.f;
    #pragma unroll 8
    for (int l = 0; l < LQ; l++) acc = fmaf(es[wf*LQ + l], qs[l*8 + dd], acc);
    out[OUT_QUERYCODE + (b*WF + wf)*DD + seg*8 + dd] = acc;
}

// ============================================================
extern "C" void kernel_launch(void* const* d_in, const int* in_sizes, int n_in,
                              void* d_out, int out_size) {
    const float* query    = (const float*)d_in[0];
    const float* fragment = (const float*)d_in[1];
    const float* qmask    = (const float*)d_in[2];
    const float* fmask    = (const float*)d_in[3];
    const float* projW    = (const float*)d_in[4];
    const float* projb    = (const float*)d_in[5];
    const float* saW      = (const float*)d_in[6];
    const float* qattW    = (const float*)d_in[7];
    const float* fattW    = (const float*)d_in[8];
    const float* qfW      = (const float*)d_in[9];
    const float* gatew    = (const float*)d_in[10];
    const float* valw     = (const float*)d_in[11];
    float* out = (float*)d_out;
    float* outq = out + OUT_QUERY;

    const int smemPA = 26624 * (int)sizeof(float);   // 106496
    const int smemQF = QW_TOT * (int)sizeof(float);  // 100864
    cudaFuncSetAttribute(k_projatt, cudaFuncAttributeMaxDynamicSharedMemorySize, smemPA);
    cudaFuncSetAttribute(k_qf_mma, cudaFuncAttributeMaxDynamicSharedMemorySize, smemQF);

    k_projatt<<<576, 256, smemPA>>>(query, fragment, projW, projb, qattW, fattW, outq);
    k_fragcode<<<BB*WF, 128>>>(saW, fmask, out);
    k_qf_mma<<<512, 256, smemQF>>>(qfW, outq);
    k_fin_a<<<BB*WF, 512>>>(gatew, valw, qmask, out);
    k_fin_b<<<64, 128>>>(outq, out);
}

// round 12
// speedup vs baseline: 1.2149x; 1.2149x over previous
#include <cuda_runtime.h>
#include <cuda_bf16.h>
#include <math.h>
#include <stdint.h>

#define BB 4
#define LQ 128
#define LF 64
#define NW 2
#define NFR 8
#define EE 128
#define DD 128
#define VV 64
#define WF (NW*NFR)   // 16

// ---- output layout (concatenated in reference tuple order) ----
#define OUT_FRAGCODE  0
#define OUT_QUERYCODE (BB*WF*DD)
#define OUT_SELFATT   (2*BB*WF*DD)
#define OUT_GATE      (2*BB*WF*DD + BB*WF*LF)
#define OUT_QUERY     (OUT_GATE + BB*WF*LQ)

// ---- scratch ----
__device__ float g_fproj[BB*WF*LF*DD];   // projected fragment (b,wf,lf,d)
__device__ float g_qatt [BB*LQ*VV];      // q_att (b,lq,v)
__device__ float g_fatt [BB*WF*LF*VV];   // f_att (b,wf,lf,v)
__device__ float g_pmax [512*64*64];     // partial maxes [bwf*8+lqh*4+lfq][64][64] (8MB)

// bf16 split helpers
__device__ __forceinline__ uint32_t pack_bf16x2(float lo_val, float hi_val) {
    uint32_t r;
    asm("cvt.rn.bf16x2.f32 %0, %1, %2;" : "=r"(r) : "f"(hi_val), "f"(lo_val));
    return r;
}
__device__ __forceinline__ float bf16lo_f32(uint32_t u) { return __uint_as_float(u << 16); }
__device__ __forceinline__ float bf16hi_f32(uint32_t u) { return __uint_as_float(u & 0xffff0000u); }
__device__ __forceinline__ void split2(float x0, float x1, uint32_t& hi, uint32_t& lo) {
    hi = pack_bf16x2(x0, x1);
    float r0 = x0 - bf16lo_f32(hi);
    float r1 = x1 - bf16hi_f32(hi);
    lo = pack_bf16x2(r0, r1);
}

// mma.sync m16n8k16 row.col f32.bf16.bf16.f32
__device__ __forceinline__ void mma16816(float* c, const uint32_t* a, const uint32_t* b) {
    asm volatile(
        "mma.sync.aligned.m16n8k16.row.col.f32.bf16.bf16.f32 "
        "{%0,%1,%2,%3}, {%4,%5,%6,%7}, {%8,%9}, {%0,%1,%2,%3};"
        : "+f"(c[0]), "+f"(c[1]), "+f"(c[2]), "+f"(c[3])
        : "r"(a[0]), "r"(a[1]), "r"(a[2]), "r"(a[3]), "r"(b[0]), "r"(b[1]));
}

// ============================================================
// Kernel A: fused projection + attention-weight GEMMs, tiled.
// grid 576 = 64 q-groups + 512 frag-groups, 8 rows each, 256 thr.
// (the all-zero-row mask in _project is a mathematical no-op)
// ============================================================
__global__ void __launch_bounds__(256) k_projatt(
    const float* __restrict__ query, const float* __restrict__ frag,
    const float* __restrict__ W, const float* __restrict__ bias,
    const float* __restrict__ qattW, const float* __restrict__ fattW,
    float* __restrict__ outq) {
    extern __shared__ float s[];
    float* Wsh  = s;            // 16384
    float* AWsh = s + 16384;    // 8192
    float* xsh  = s + 24576;    // 1024
    float* psh  = s + 25600;    // 1024   total 26624 floats
    int g = blockIdx.x;
    int tid = threadIdx.x;
    bool isq = (g < 64);

    {
        const float4* Wv = (const float4*)W;
        float4* Ws = (float4*)Wsh;
        #pragma unroll
        for (int i = 0; i < 16; i++) Ws[tid + 256*i] = Wv[tid + 256*i];
        const float4* Av = (const float4*)(isq ? qattW : fattW);
        float4* As = (float4*)AWsh;
        #pragma unroll
        for (int i = 0; i < 8; i++) As[tid + 256*i] = Av[tid + 256*i];
        const float* src = isq ? (query + (size_t)g*8*EE)
                               : (frag  + (size_t)(g-64)*8*EE);
        ((float4*)xsh)[tid] = ((const float4*)src)[tid];
    }
    __syncthreads();

    {
        int j = tid & 127, rh = tid >> 7;
        float bj = __ldg(&bias[j]);
        float a0 = bj, a1 = bj, a2 = bj, a3 = bj;
        #pragma unroll 4
        for (int d = 0; d < EE; d++) {
            float w = Wsh[d*DD + j];
            a0 = fmaf(xsh[(rh+0)*EE + d], w, a0);
            a1 = fmaf(xsh[(rh+2)*EE + d], w, a1);
            a2 = fmaf(xsh[(rh+4)*EE + d], w, a2);
            a3 = fmaf(xsh[(rh+6)*EE + d], w, a3);
        }
        psh[(rh+0)*DD + j] = a0; psh[(rh+2)*DD + j] = a1;
        psh[(rh+4)*DD + j] = a2; psh[(rh+6)*DD + j] = a3;
        float* dst = isq ? (outq + (size_t)g*8*DD)
                         : (g_fproj + (size_t)(g-64)*8*DD);
        dst[(rh+0)*DD + j] = a0; dst[(rh+2)*DD + j] = a1;
        dst[(rh+4)*DD + j] = a2; dst[(rh+6)*DD + j] = a3;
    }
    __syncthreads();

    {
        int j2 = tid & 63, r2 = tid >> 6;
        float a0 = 0.f, a1 = 0.f;
        #pragma unroll 4
        for (int d = 0; d < DD; d++) {
            float w = AWsh[d*VV + j2];
            a0 = fmaf(psh[(r2+0)*DD + d], w, a0);
            a1 = fmaf(psh[(r2+4)*DD + d], w, a1);
        }
        float* dst = isq ? (g_qatt + (size_t)g*8*VV)
                         : (g_fatt + (size_t)(g-64)*8*VV);
        dst[(r2+0)*VV + j2] = a0;
        dst[(r2+4)*VV + j2] = a1;
    }
}

// ============================================================
// Kernel B: fragment self-attention softmax + frag_code
// ============================================================
__global__ void k_fragcode(const float* __restrict__ saW,
                           const float* __restrict__ fmask,
                           float* __restrict__ out) {
    int bwf = blockIdx.x;
    int w = (bwf % WF) / NFR;
    const float* fbase = g_fproj + (size_t)bwf*LF*DD;
    __shared__ float att[LF];
    __shared__ float s_inv;
    int t = threadIdx.x;
    if (t < LF) {
        const float* fr = fbase + t*DD;
        const float* sw = saW + w*DD;
        float acc = 0.f;
        #pragma unroll 8
        for (int d = 0; d < DD; d++) acc += fr[d]*sw[d];
        att[t] = expf(acc) * fmask[bwf*LF + t];
    }
    __syncthreads();
    if (t == 0) {
        float ss = 0.f;
        for (int l = 0; l < LF; l++) ss += att[l];
        s_inv = 1.f / (ss + 1e-7f);
    }
    __syncthreads();
    float inv = s_inv;
    if (t < LF) out[OUT_SELFATT + bwf*LF + t] = att[t]*inv;
    float acc = 0.f;
    #pragma unroll 8
    for (int l = 0; l < LF; l++) acc += att[l]*inv*fbase[l*DD + t];
    out[OUT_FRAGCODE + bwf*DD + t] = acc;
}

// ============================================================
// Kernel C (hot, HMMA): per (bwf, lq-half64, lf-quarter16):
//   partial max over lf of (f_att + q @ (f_lf ⊙ W_qf))
// A = q 64x128 split bf16 hi/lo ONCE, fragments register-resident.
// Per lf: B' = f⊙W split hi/lo in smem; 3-pass split GEMM via
// mma.sync.m16n8k16 (Ahi·Bhi + Ahi·Blo + Alo·Bhi), fp32 accum.
// 8 warps: warp = (m-strip 16 of 64) x (n-half 32 of 64).
// (round-7 version verbatim — best measured; fragment-layout and
//  lq-merge variants both regressed)
// ============================================================
// smem word offsets
#define QW_WT   0                      // W transposed [64][130] = 8320
#define QW_AH   8320                   // [64][68] u32 = 4352
#define QW_AL   (QW_AH + 4352)
#define QW_BH   (QW_AL + 4352)         // [64][68] u32 = 4352
#define QW_BL   (QW_BH + 4352)
#define QW_TOT  (QW_BL + 4352)         // 25728 words = 102912 B

__global__ void __launch_bounds__(256) k_qf_mma(
    const float* __restrict__ qfW, const float* __restrict__ outq) {
    extern __shared__ float s[];
    float* Wt = s + QW_WT;                       // [v][130] fp32
    uint32_t* Ah = (uint32_t*)(s + QW_AH);       // [row][68]
    uint32_t* Al = (uint32_t*)(s + QW_AL);
    uint32_t* Bh = (uint32_t*)(s + QW_BH);       // [v][68]
    uint32_t* Bl = (uint32_t*)(s + QW_BL);

    int blk = blockIdx.x;            // 512 = bwf(64) x lqh(2) x lfq(4)
    int lfq = blk & 3;
    int lqh = (blk >> 2) & 1;
    int bwf = blk >> 3;
    int b = bwf >> 4;
    int lfbase = lfq * 16;
    int tid = threadIdx.x, lane = tid & 31, wid = tid >> 5;
    int m0 = (wid & 3) * 16;         // m-strip within 64
    int n0 = (wid >> 2) * 32;        // n-half

    // stage W transposed: Wt[v][d]
    for (int idx = tid; idx < DD*VV; idx += 256) {
        int d = idx >> 6, v = idx & 63;
        Wt[v*130 + d] = qfW[idx];
    }
    // convert A (q tile 64x128) -> bf16 hi/lo words [row][68]
    for (int idx = tid; idx < 64*64; idx += 256) {
        int row = idx >> 6, cp = idx & 63;
        float2 qv = *(const float2*)&outq[((size_t)(b*LQ + lqh*64 + row))*DD + cp*2];
        uint32_t hi, lo;
        split2(qv.x, qv.y, hi, lo);
        Ah[row*68 + cp] = hi;
        Al[row*68 + cp] = lo;
    }
    __syncthreads();

    // load A fragments (register-resident for all lf)
    uint32_t ah[8][4], al[8][4];
    {
        int r = m0 + (lane >> 2);
        #pragma unroll
        for (int k = 0; k < 8; k++) {
            int c = k*8 + (lane & 3);
            ah[k][0] = Ah[r*68 + c];       ah[k][1] = Ah[(r+8)*68 + c];
            ah[k][2] = Ah[r*68 + c + 4];   ah[k][3] = Ah[(r+8)*68 + c + 4];
            al[k][0] = Al[r*68 + c];       al[k][1] = Al[(r+8)*68 + c];
            al[k][2] = Al[r*68 + c + 4];   al[k][3] = Al[(r+8)*68 + c + 4];
        }
    }

    float mx[4][4];
    #pragma unroll
    for (int t = 0; t < 4; t++)
        #pragma unroll
        for (int i = 0; i < 4; i++) mx[t][i] = -INFINITY;

    for (int k16 = 0; k16 < 16; k16++) {
        int lf = lfbase + k16;
        __syncthreads();     // prior-iter B reads complete before overwrite

        // convert B' = f ⊙ W -> bf16 hi/lo [v][68]
        const float* fptr = g_fproj + ((size_t)bwf*LF + lf)*DD;
        for (int idx = tid; idx < 64*64; idx += 256) {
            int v = idx >> 6, cp = idx & 63;
            float2 wv = *(const float2*)&Wt[v*130 + cp*2];
            float2 fv = *(const float2*)&fptr[cp*2];
            uint32_t hi, lo;
            split2(wv.x*fv.x, wv.y*fv.y, hi, lo);
            Bh[v*68 + cp] = hi;
            Bl[v*68 + cp] = lo;
        }
        __syncthreads();

        // 3-pass split GEMM, C[16x32] per warp
        float cc[4][4];
        #pragma unroll
        for (int t = 0; t < 4; t++)
            #pragma unroll
            for (int i = 0; i < 4; i++) cc[t][i] = 0.f;

        #pragma unroll
        for (int k = 0; k < 8; k++) {
            #pragma unroll
            for (int t = 0; t < 4; t++) {
                int v = n0 + t*8 + (lane >> 2);
                int c = k*8 + (lane & 3);
                uint32_t bh[2], bl[2];
                bh[0] = Bh[v*68 + c];  bh[1] = Bh[v*68 + c + 4];
                bl[0] = Bl[v*68 + c];  bl[1] = Bl[v*68 + c + 4];
                mma16816(cc[t], ah[k], bh);
                mma16816(cc[t], ah[k], bl);
                mma16816(cc[t], al[k], bh);
            }
        }

        // running max of (cc + f_att)
        const float* fa = g_fatt + ((size_t)bwf*LF + lf)*VV;
        #pragma unroll
        for (int t = 0; t < 4; t++) {
            int col = n0 + t*8 + (lane & 3)*2;
            float2 f2 = *(const float2*)&fa[col];
            mx[t][0] = fmaxf(mx[t][0], cc[t][0] + f2.x);
            mx[t][1] = fmaxf(mx[t][1], cc[t][1] + f2.y);
            mx[t][2] = fmaxf(mx[t][2], cc[t][2] + f2.x);
            mx[t][3] = fmaxf(mx[t][3], cc[t][3] + f2.y);
        }
    }

    // write partial-max tile [64][64]
    float* outp = g_pmax + (size_t)blk * 4096;
    int r0 = m0 + (lane >> 2);
    #pragma unroll
    for (int t = 0; t < 4; t++) {
        int col = n0 + t*8 + (lane & 3)*2;
        *(float2*)&outp[r0*64 + col]     = make_float2(mx[t][0], mx[t][1]);
        *(float2*)&outp[(r0+8)*64 + col] = make_float2(mx[t][2], mx[t][3]);
    }
}

// ============================================================
// Kernel D: fused finalize, 512 threads, ONE launch.
// Phase 1: lq(128) x vq(4) decomposition over the 8MB g_pmax
//   stream (4x MLP — the measured fix for the latency-bound read):
//   combine 4 lf-quarters, + q_att, gate/val partial dots.
// Phase 2: tree-reduce e2 over LQ; query_code with 4-way l-split,
//   e2 kept in smem (no global round-trip, no extra kernel).
// ============================================================
__global__ void __launch_bounds__(512) k_fin(
    const float* __restrict__ gate_w,
    const float* __restrict__ val_w,
    const float* __restrict__ qmask,
    const float* __restrict__ outq,
    float* __restrict__ out) {
    int bwf = blockIdx.x;
    int b = bwf >> 4;
    int tid = threadIdx.x;
    int lq = tid & 127, vq = tid >> 7;
    __shared__ float gsh[4][LQ];
    __shared__ float vsh[4][LQ];
    __shared__ float esh[LQ];
    __shared__ float red[LQ];
    __shared__ float inv_s;

    // phase 1: gate/val partial dots over this thread's 16-v quarter
    {
        int lqh = lq >> 6, r = lq & 63;
        const float* base = g_pmax + ((size_t)(bwf*8 + lqh*4)) * 4096 + r*64;
        const float4* qa = (const float4*)(g_qatt + (size_t)(b*LQ + lq)*VV);
        const float4* gw = (const float4*)gate_w;
        const float4* vw = (const float4*)val_w;
        float gs = 0.f, vs = 0.f;
        #pragma unroll
        for (int i = vq*4; i < vq*4 + 4; i++) {
            float4 a0 = *(const float4*)&base[i*4];
            float4 a1 = *(const float4*)&base[4096 + i*4];
            float4 a2 = *(const float4*)&base[2*4096 + i*4];
            float4 a3 = *(const float4*)&base[3*4096 + i*4];
            float4 q = qa[i], g4 = gw[i], v4 = vw[i];
            float mxv = fmaxf(fmaxf(a0.x, a1.x), fmaxf(a2.x, a3.x)) + q.x;
            float myv = fmaxf(fmaxf(a0.y, a1.y), fmaxf(a2.y, a3.y)) + q.y;
            float mzv = fmaxf(fmaxf(a0.z, a1.z), fmaxf(a2.z, a3.z)) + q.z;
            float mwv = fmaxf(fmaxf(a0.w, a1.w), fmaxf(a2.w, a3.w)) + q.w;
            gs += mxv*g4.x + myv*g4.y + mzv*g4.z + mwv*g4.w;
            vs += mxv*v4.x + myv*v4.y + mzv*v4.z + mwv*v4.w;
        }
        gsh[vq][lq] = gs;
        vsh[vq][lq] = vs;
    }
    __syncthreads();

    if (tid < LQ) {
        float gsum = gsh[0][tid] + gsh[1][tid] + gsh[2][tid] + gsh[3][tid];
        float vsum = vsh[0][tid] + vsh[1][tid] + vsh[2][tid] + vsh[3][tid];
        float qm = qmask[b*LQ + tid];
        out[OUT_GATE + bwf*LQ + tid] = (1.f / (1.f + expf(-gsum))) * qm;
        float e2 = expf(vsum) * qm;
        esh[tid] = e2;
        red[tid] = e2;
    }
    __syncthreads();
    #pragma unroll
    for (int off = 64; off > 0; off >>= 1) {
        if (tid < off) red[tid] += red[tid + off];
        __syncthreads();
    }
    if (tid == 0) inv_s = 1.f / (red[0] + 1e-7f);
    __syncthreads();

    // phase 2: query_code[d] = inv * sum_l e2[l] * q[b,l,d], l split 4 ways
    {
        int d = lq;                       // 0..127
        const float* qb = outq + ((size_t)(b*LQ + vq*32))*DD + d;
        float acc = 0.f;
        #pragma unroll 8
        for (int l = 0; l < 32; l++)
            acc = fmaf(esh[vq*32 + l], qb[(size_t)l*DD], acc);
        gsh[vq][d] = acc;                 // reuse gsh (done with it)
    }
    __syncthreads();
    if (tid < LQ) {
        float qc = gsh[0][tid] + gsh[1][tid] + gsh[2][tid] + gsh[3][tid];
        out[OUT_QUERYCODE + bwf*DD + tid] = qc * inv_s;
    }
}

// ============================================================
extern "C" void kernel_launch(void* const* d_in, const int* in_sizes, int n_in,
                              void* d_out, int out_size) {
    const float* query    = (const float*)d_in[0];
    const float* fragment = (const float*)d_in[1];
    const float* qmask    = (const float*)d_in[2];
    const float* fmask    = (const float*)d_in[3];
    const float* projW    = (const float*)d_in[4];
    const float* projb    = (const float*)d_in[5];
    const float* saW      = (const float*)d_in[6];
    const float* qattW    = (const float*)d_in[7];
    const float* fattW    = (const float*)d_in[8];
    const float* qfW      = (const float*)d_in[9];
    const float* gatew    = (const float*)d_in[10];
    const float* valw     = (const float*)d_in[11];
    float* out = (float*)d_out;
    float* outq = out + OUT_QUERY;

    const int smemPA = 26624 * (int)sizeof(float);   // 106496
    const int smemQF = QW_TOT * (int)sizeof(float);  // 102912
    cudaFuncSetAttribute(k_projatt, cudaFuncAttributeMaxDynamicSharedMemorySize, smemPA);
    cudaFuncSetAttribute(k_qf_mma, cudaFuncAttributeMaxDynamicSharedMemorySize, smemQF);

    k_projatt<<<576, 256, smemPA>>>(query, fragment, projW, projb, qattW, fattW, outq);
    k_fragcode<<<BB*WF, 128>>>(saW, fmask, out);
    k_qf_mma<<<512, 256, smemQF>>>(qfW, outq);
    k_fin<<<BB*WF, 512>>>(gatew, valw, qmask, outq, out);
}